// round 16
// baseline (speedup 1.0000x reference)
#include <cuda_runtime.h>
#include <mma.h>
#include <cstdint>
#include <cstddef>

using namespace nvcuda;

// ---------------------------------------------------------------------------
// B=16, T=64, HW=7 (49), D=768, N=12 heads, C=64, EPS=1e-5
//   WeffT[s*768+n*64+d, hw*768+k] = sum_c W_qkv[k, s*768+n*64+c]*Wp_s[d,c,hw]
//   qkv_pooled[bt, nd] = sum_kk x[bt, kk] * WeffT[nd, kk]
// -> ONE GEMM (1024 x 2304 x 37632), epilogue bias+LayerNorm.
// K1 tcgen05 body: cp.async producers + mbarrier full/empty ring (4 stages),
// warp-0-elected MMA consumer, NO per-iteration __syncthreads.
// ROUND-15 FIX: cp.async.mbarrier.arrive must be the .noinc variant — the
// plain form pre-increments the pending count (net zero) so full[] never
// flipped -> deadlock (round-14 timeout).
// ---------------------------------------------------------------------------
#define BT     1024
#define D3     2304
#define KBIG   37632        // 49*768
#define NHEAD  12
#define HW2    49
#define KTILES (KBIG / 32)  // 1176 (divisible by 4)

#if defined(__CUDA_ARCH_FEAT_SM103_ALL) || defined(__CUDA_ARCH_FEAT_SM100_ALL) || defined(__CUDA_ARCH_FEAT_SM101_ALL)
#define HAS_TCGEN05 1
#else
#define HAS_TCGEN05 0
#endif

// ---------------------------------------------------------------------------
// Device scratch (statics; no runtime allocation)
// ---------------------------------------------------------------------------
__device__ float g_weffT[(size_t)D3 * KBIG];   // [n_global][k_global], 346.8 MB
__device__ float g_xtf[(size_t)BT * KBIG];     // tf32-rounded x, 154 MB
__device__ float g_wpT[3 * HW2 * 64 * 64];     // Wp transposed [s][hw][c][d]
__device__ float g_qb[BT * 768];               // (B,N,T,C) post-LN q
__device__ float g_kb[BT * 768];
__device__ float g_vb[BT * 768];
__device__ float g_att[BT * 768];              // (B,T,768) attention out

// ---------------------------------------------------------------------------
// Common helpers
// ---------------------------------------------------------------------------
__device__ __forceinline__ float f2tf(float x) {
    uint32_t u;
    asm("cvt.rna.tf32.f32 %0, %1;" : "=r"(u) : "f"(x));
    return __uint_as_float(u);
}
__device__ __forceinline__ float4 cvt4(float4 v) {
    float4 w;
    w.x = f2tf(v.x); w.y = f2tf(v.y); w.z = f2tf(v.z); w.w = f2tf(v.w);
    return w;
}

typedef wmma::fragment<wmma::matrix_a, 16, 16, 8, wmma::precision::tf32, wmma::row_major> FragA;
typedef wmma::fragment<wmma::matrix_b, 16, 16, 8, wmma::precision::tf32, wmma::row_major> FragB;
typedef wmma::fragment<wmma::matrix_b, 16, 16, 8, wmma::precision::tf32, wmma::col_major> FragBc;
typedef wmma::fragment<wmma::accumulator, 16, 16, 8, float> FragC;

__device__ __forceinline__ uint32_t elect_one_pred() {
    uint32_t pred;
    asm volatile(
        "{\n\t.reg .pred p;\n\t"
        "elect.sync _|p, 0xFFFFFFFF;\n\t"
        "selp.b32 %0, 1, 0, p;\n\t}"
        : "=r"(pred));
    return pred;
}
__device__ __forceinline__ uint32_t smem_to_u32(const void* p) {
    uint32_t a;
    asm("{ .reg .u64 t; cvta.to.shared.u64 t, %1; cvt.u32.u64 %0, t; }"
        : "=r"(a) : "l"(p));
    return a;
}

#define MBARRIER_INIT(addr, cnt) \
    asm volatile("mbarrier.init.shared.b64 [%0], %1;" :: "r"(addr), "r"(cnt) : "memory")

#define MBARRIER_WAIT_PARITY(addr, par) do {                                   \
    uint32_t _m = (addr), _p = (par), _d;                                      \
    asm volatile(                                                              \
        "{\n\t.reg .pred p;\n\t"                                               \
        "mbarrier.try_wait.parity.acquire.cta.shared::cta.b64 p, [%1], %2;\n\t"\
        "selp.b32 %0, 1, 0, p;\n\t}"                                           \
        : "=r"(_d) : "r"(_m), "r"(_p) : "memory");                             \
    if (!_d) {                                                                 \
        asm volatile(                                                          \
            "{\n\t.reg .pred P1;\n\t"                                          \
            "WL_%=:\n\t"                                                       \
            "mbarrier.try_wait.parity.acquire.cta.shared::cta.b64 P1, [%0], %1, 0x989680;\n\t" \
            "@P1 bra.uni WD_%=;\n\t"                                           \
            "bra.uni WL_%=;\n\t"                                               \
            "WD_%=:\n\t}"                                                      \
            :: "r"(_m), "r"(_p) : "memory");                                   \
    }                                                                          \
} while (0)

#define SW128(off) ((off) ^ (((off) >> 3) & 0x70))

// cp.async (Ampere-style async copy; no tensormap needed)
#define CP_ASYNC16(dst_u32, src_ptr) \
    asm volatile("cp.async.cg.shared.global [%0], [%1], 16;" \
                 :: "r"(dst_u32), "l"(src_ptr) : "memory")
// .noinc: arrive WITHOUT pre-incrementing pending count (barrier pre-armed
// with 256). The plain form is +1-then-arrive = net zero = never flips.
#define CP_ASYNC_MBAR_ARRIVE(mb) \
    asm volatile("cp.async.mbarrier.arrive.noinc.shared.b64 [%0];" :: "r"(mb) : "memory")

// ---------------------------------------------------------------------------
// tcgen05-only helpers
// ---------------------------------------------------------------------------
#define TCGEN05_ALLOC(res, n) \
    asm volatile("tcgen05.alloc.cta_group::1.sync.aligned.shared::cta.b32 [%0], %1;" \
                 :: "r"((uint32_t)(res)), "r"((uint32_t)(n)) : "memory")
#define TCGEN05_DEALLOC(tm, n) \
    asm volatile("tcgen05.dealloc.cta_group::1.sync.aligned.b32 %0, %1;" \
                 :: "r"(tm), "r"((uint32_t)(n)))
#define TCGEN05_RELINQ() \
    asm volatile("tcgen05.relinquish_alloc_permit.cta_group::1.sync.aligned;")
#define TCGEN05_COMMIT(mb) \
    asm volatile("tcgen05.commit.cta_group::1.mbarrier::arrive::one.shared::cluster.b64 [%0];" \
                 :: "r"((uint32_t)(mb)) : "memory")
#define TCGEN05_FENCE_AFTER() \
    asm volatile("tcgen05.fence::after_thread_sync;" ::: "memory")
#define TCGEN05_FENCE_BEFORE() \
    asm volatile("tcgen05.fence::before_thread_sync;" ::: "memory")
#define TCGEN05_WAIT_LD() \
    asm volatile("tcgen05.wait::ld.sync.aligned;" ::: "memory")
#define FENCE_ASYNC_SHARED() \
    asm volatile("fence.proxy.async.shared::cta;" ::: "memory")

#define TCGEN05_LD_X32(r, tm)                                                  \
    asm volatile(                                                              \
        "tcgen05.ld.sync.aligned.32x32b.x32.b32 "                              \
        "{%0, %1, %2, %3, %4, %5, %6, %7, "                                    \
        " %8, %9, %10, %11, %12, %13, %14, %15, "                              \
        " %16, %17, %18, %19, %20, %21, %22, %23, "                            \
        " %24, %25, %26, %27, %28, %29, %30, %31}, [%32];"                     \
        : "=r"((r)[0]),  "=r"((r)[1]),  "=r"((r)[2]),  "=r"((r)[3]),           \
          "=r"((r)[4]),  "=r"((r)[5]),  "=r"((r)[6]),  "=r"((r)[7]),           \
          "=r"((r)[8]),  "=r"((r)[9]),  "=r"((r)[10]), "=r"((r)[11]),          \
          "=r"((r)[12]), "=r"((r)[13]), "=r"((r)[14]), "=r"((r)[15]),          \
          "=r"((r)[16]), "=r"((r)[17]), "=r"((r)[18]), "=r"((r)[19]),          \
          "=r"((r)[20]), "=r"((r)[21]), "=r"((r)[22]), "=r"((r)[23]),          \
          "=r"((r)[24]), "=r"((r)[25]), "=r"((r)[26]), "=r"((r)[27]),          \
          "=r"((r)[28]), "=r"((r)[29]), "=r"((r)[30]), "=r"((r)[31])           \
        : "r"(tm))

#define TCGEN05_MMA_TF32_SS(d_tmem, a_desc, b_desc, idesc, enable)             \
    asm volatile(                                                              \
        "{\n\t.reg .pred p;\n\t"                                               \
        "setp.ne.u32 p, %4, 0;\n\t"                                            \
        "tcgen05.mma.cta_group::1.kind::tf32 [%0], %1, %2, %3, {%5, %5, %5, %5}, p;\n\t" \
        "}"                                                                    \
        :: "r"(d_tmem), "l"(a_desc), "l"(b_desc), "r"(idesc),                  \
           "r"((uint32_t)(enable)), "r"(0u)                                    \
        : "memory")

// SW128 descriptor: layout=2, version=1 (Blackwell), SBO=64, LBO=1 (128B rows)
static constexpr uint64_t SMEM_DESC_BASE_SW128 =
    (uint64_t(2) << 61) | (uint64_t(1) << 46) | (uint64_t(64) << 32) | (uint64_t(1) << 16);
#define MAKE_SMEM_DESC(a) (SMEM_DESC_BASE_SW128 | ((uint64_t)((a) >> 4) & 0x3FFF))

// idesc kind::tf32: dformat F32=1 [4:5], atype TF32=2 [7:9], btype TF32=2
// [10:12], N/8 [17:22] = 16 (N=128), M/16 [24:28] = 8 (M=128)
#define IDESC_TF32 ((1u << 4) | (2u << 7) | (2u << 10) | (16u << 17) | (8u << 24))

// ---------------------------------------------------------------------------
// K00: transpose Wp (d,c,hw) -> g_wpT[s][hw][c][d]  (+ tf32 pre-round)
// ---------------------------------------------------------------------------
__global__ void __launch_bounds__(256) transpose_wp_kernel(
    const float* __restrict__ wq, const float* __restrict__ wk, const float* __restrict__ wv)
{
    int idx = blockIdx.x * 256 + threadIdx.x;
    if (idx >= 3 * HW2 * 4096) return;
    int s = idx / (HW2 * 4096);
    int r = idx - s * (HW2 * 4096);
    int d  = r & 63;
    int c  = (r >> 6) & 63;
    int hw = r >> 12;
    const float* w = (s == 0) ? wq : (s == 1) ? wk : wv;
    g_wpT[idx] = f2tf(w[d * (64 * HW2) + c * HW2 + hw]);
}

// ---------------------------------------------------------------------------
// K01: pre-round x to tf32 (float4 per thread)
// ---------------------------------------------------------------------------
__global__ void __launch_bounds__(256) preround_x_kernel(const float* __restrict__ x)
{
    size_t i = ((size_t)blockIdx.x * 256 + threadIdx.x) * 4;
    if (i >= (size_t)BT * KBIG) return;
    float4 v = *reinterpret_cast<const float4*>(x + i);
    *reinterpret_cast<float4*>(g_xtf + i) = cvt4(v);
}

// ---------------------------------------------------------------------------
// K0: WeffT precompute, stored [n_global][k_global] (K-major), tf32-rounded.
// ---------------------------------------------------------------------------
__global__ void __launch_bounds__(256) weff_kernel(const float* __restrict__ Wqkv)
{
    __shared__ float As[128][36];
    __shared__ float Bs[32][72];

    const int tid = threadIdx.x, warp = tid >> 5;
    const int y = blockIdx.y;
    const int s = y / (HW2 * NHEAD);
    const int rem = y - s * (HW2 * NHEAD);
    const int hw = rem / NHEAD;
    const int n  = rem - hw * NHEAD;
    const int m0 = blockIdx.x * 128;
    const int coloff = s * 768 + n * 64;
    const float* wpT = g_wpT + (size_t)(s * HW2 + hw) * 4096;
    const int wm = (warp >> 1) * 32;
    const int wn = (warp & 1) * 32;

    FragC acc[2][2];
#pragma unroll
    for (int i = 0; i < 2; i++)
#pragma unroll
        for (int j = 0; j < 2; j++) wmma::fill_fragment(acc[i][j], 0.f);

#pragma unroll
    for (int kt = 0; kt < 2; kt++) {
#pragma unroll
        for (int it = 0; it < 4; it++) {
            int idx = tid + it * 256;
            int r = idx >> 3, q = (idx & 7) << 2;
            float4 v = *reinterpret_cast<const float4*>(
                Wqkv + (size_t)(m0 + r) * D3 + coloff + kt * 32 + q);
            *reinterpret_cast<float4*>(&As[r][q]) = cvt4(v);
        }
#pragma unroll
        for (int it = 0; it < 2; it++) {
            int idx = tid + it * 256;
            int rr = idx >> 4, dd = (idx & 15) << 2;
            *reinterpret_cast<float4*>(&Bs[rr][dd]) =
                *reinterpret_cast<const float4*>(wpT + (kt * 32 + rr) * 64 + dd);
        }
        __syncthreads();

#pragma unroll
        for (int kk = 0; kk < 4; kk++) {
            FragA af[2];
            FragB bf[2];
#pragma unroll
            for (int i = 0; i < 2; i++)
                wmma::load_matrix_sync(af[i], &As[wm + i * 16][kk * 8], 36);
#pragma unroll
            for (int j = 0; j < 2; j++)
                wmma::load_matrix_sync(bf[j], &Bs[kk * 8][wn + j * 16], 72);
#pragma unroll
            for (int i = 0; i < 2; i++)
#pragma unroll
                for (int j = 0; j < 2; j++)
                    wmma::mma_sync(acc[i][j], af[i], bf[j], acc[i][j]);
        }
        __syncthreads();
    }

#pragma unroll
    for (int i = 0; i < 2; i++)
#pragma unroll
        for (int j = 0; j < 2; j++) {
#pragma unroll
            for (int e = 0; e < acc[i][j].num_elements; e++)
                acc[i][j].x[e] = f2tf(acc[i][j].x[e]);
            float* dst = g_weffT +
                (size_t)(coloff + wn + j * 16) * KBIG + (hw * 768 + m0 + wm + i * 16);
            wmma::store_matrix_sync(dst, acc[i][j], KBIG, wmma::mem_col_major);
        }
}

// ---------------------------------------------------------------------------
// K1: fused GEMM (1024 x 2304 x 37632) + bias + LayerNorm epilogue.
// grid (18, 8) = 144 CTAs, 256 threads.
// ---------------------------------------------------------------------------
#define ST_A(s)  ((s) * 16384)
#define ST_B(s)  (65536 + (s) * 16384)
#define OFF_TM   131072
#define OFF_FULL 131080                     // full[4] : 8B each
#define OFF_EMPT 131112                     // empty[4]: 8B each
#define K1_SMEM_BYTES 131200

__global__ void __launch_bounds__(256, 1) qkv_pool_ln_tc(
    const float* __restrict__ bq, const float* __restrict__ bk, const float* __restrict__ bv,
    const float* __restrict__ gq, const float* __restrict__ gk, const float* __restrict__ gv,
    const float* __restrict__ eq, const float* __restrict__ ek, const float* __restrict__ ev)
{
#if HAS_TCGEN05
    // =======================================================================
    // tcgen05 tf32 SS body — cp.async producers + mbarrier ring, no per-iter
    // __syncthreads. Consumer = warp-0 elected thread.
    // =======================================================================
    extern __shared__ char smem[];
    const uint32_t sb = smem_to_u32(smem);
    const int tid = threadIdx.x, warp = tid >> 5, lane = tid & 31;
    const int m0 = blockIdx.y * 128, n0 = blockIdx.x * 128;

    if (warp == 0) TCGEN05_ALLOC(sb + OFF_TM, 128);
    if (tid == 0) {
#pragma unroll
        for (int s = 0; s < 4; s++) {
            MBARRIER_INIT(sb + OFF_FULL + s * 8, 256);  // 256 noinc arrives
            MBARRIER_INIT(sb + OFF_EMPT + s * 8, 1);    // 1 commit arrive
        }
    }
    __syncthreads();
    uint32_t tmem;
    asm volatile("ld.shared.b32 %0, [%1];" : "=r"(tmem) : "r"(sb + OFF_TM));

    const int rA  = tid >> 3;              // base row, +32 per it
    const int q16 = (tid & 7) << 4;        // byte offset within 128B row
    uint32_t swoff[4];
#pragma unroll
    for (int it = 0; it < 4; it++)
        swoff[it] = SW128((uint32_t)((it * 32 + rA) * 128 + q16));

    const float* Ap = g_xtf   + (size_t)(m0 + rA) * KBIG + (q16 >> 2);
    const float* Bp = g_weffT + (size_t)(n0 + rA) * KBIG + (q16 >> 2);

    uint32_t cons = 0;
    if (warp == 0) cons = elect_one_pred();

    int ph_e[4] = {0, 0, 0, 0};    // tracked by ALL threads (producers)
    int ph_f[4] = {0, 0, 0, 0};    // meaningful only in consumer thread

#pragma unroll 1
    for (int i = 0; i < KTILES; i++) {
        const int s = i & 3;
        if (i >= 4) {
            MBARRIER_WAIT_PARITY(sb + OFF_EMPT + s * 8, ph_e[s]);
            ph_e[s] ^= 1;
        }
        const int k0 = i * 32;
        const uint32_t abase = sb + ST_A(s);
        const uint32_t bbase = sb + ST_B(s);
#pragma unroll
        for (int it = 0; it < 4; it++) {
            CP_ASYNC16(abase + swoff[it], Ap + (size_t)(it * 32) * KBIG + k0);
            CP_ASYNC16(bbase + swoff[it], Bp + (size_t)(it * 32) * KBIG + k0);
        }
        CP_ASYNC_MBAR_ARRIVE(sb + OFF_FULL + s * 8);

        if (cons) {
            MBARRIER_WAIT_PARITY(sb + OFF_FULL + s * 8, ph_f[s]);
            ph_f[s] ^= 1;
            FENCE_ASYNC_SHARED();
            const uint64_t ad = MAKE_SMEM_DESC(abase);
            const uint64_t bd = MAKE_SMEM_DESC(bbase);
#pragma unroll
            for (int kk = 0; kk < 4; kk++)
                TCGEN05_MMA_TF32_SS(tmem, ad + kk * 2, bd + kk * 2, IDESC_TF32,
                                    (i > 0) || (kk > 0));
            TCGEN05_COMMIT(sb + OFF_EMPT + s * 8);
        }
    }

    // drain: all MMA batches committed; wait final empty flips
#pragma unroll
    for (int s = 0; s < 4; s++)
        MBARRIER_WAIT_PARITY(sb + OFF_EMPT + s * 8, ph_e[s]);
    TCGEN05_FENCE_AFTER();
    __syncthreads();

    if (warp < 4) {
        float dreg[128];
        uint32_t* du = reinterpret_cast<uint32_t*>(dreg);
#pragma unroll
        for (int base = 0; base < 128; base += 32) TCGEN05_LD_X32(du + base, tmem + base);
        TCGEN05_WAIT_LD();
        TCGEN05_FENCE_BEFORE();

        const int row = warp * 32 + lane;
        const int bt = m0 + row;
        const int bb = bt >> 6, t = bt & 63;
        const int s  = n0 / 768;
        const int nh0 = (n0 - s * 768) >> 6;
        const float* bias = (s == 0) ? bq : (s == 1) ? bk : bv;
        const float* gam  = (s == 0) ? gq : (s == 1) ? gk : gv;
        const float* bet  = (s == 0) ? eq : (s == 1) ? ek : ev;
        float* outp       = (s == 0) ? g_qb : (s == 1) ? g_kb : g_vb;

#pragma unroll
        for (int hh = 0; hh < 2; hh++) {
            const int c0 = hh << 6;
            float mu = 0.f;
#pragma unroll
            for (int d = 0; d < 64; d++) mu += dreg[c0 + d] + __ldg(bias + d);
            mu *= (1.f / 64.f);
            float var = 0.f;
#pragma unroll
            for (int d = 0; d < 64; d++) {
                float v = dreg[c0 + d] + __ldg(bias + d) - mu;
                var += v * v;
            }
            var *= (1.f / 64.f);
            const float rs = rsqrtf(var + 1e-5f);
            const size_t obase = (((size_t)bb * NHEAD + nh0 + hh) * 64 + t) * 64;
#pragma unroll
            for (int d = 0; d < 64; d++) {
                float v = (dreg[c0 + d] + __ldg(bias + d) - mu) * rs;
                outp[obase + d] = v * __ldg(gam + d) + __ldg(bet + d);
            }
        }
    }
    __syncthreads();
    if (warp == 0) {
        TCGEN05_RELINQ();
        TCGEN05_DEALLOC(tmem, 128);
    }
#else
    // =======================================================================
    // wmma HMMA tf32 fallback body (reads pre-rounded g_xtf)
    // =======================================================================
    extern __shared__ char smem_c[];
    float* smemf = reinterpret_cast<float*>(smem_c);
    float (*As)[36]  = reinterpret_cast<float(*)[36]>(smemf);           // [m][k]
    float (*Bs)[36]  = reinterpret_cast<float(*)[36]>(smemf + 4608);    // [n][k]
    float (*Cs)[132] = reinterpret_cast<float(*)[132]>(smemf);          // reused

    const int tid = threadIdx.x, warp = tid >> 5;
    const int m0 = blockIdx.y * 128, n0 = blockIdx.x * 128;
    const int wm = (warp >> 2) * 64, wn = (warp & 3) * 32;

    const int r0 = tid >> 3;              // + it*32
    const int q  = (tid & 7) << 2;

    const float* Ap = g_xtf   + (size_t)(m0 + r0) * KBIG + q;
    const float* Bp = g_weffT + (size_t)(n0 + r0) * KBIG + q;

    FragC acc[4][2];
#pragma unroll
    for (int i = 0; i < 4; i++)
#pragma unroll
        for (int j = 0; j < 2; j++) wmma::fill_fragment(acc[i][j], 0.f);

    float4 ra[4], rb[4];
#pragma unroll
    for (int it = 0; it < 4; it++) {
        ra[it] = *reinterpret_cast<const float4*>(Ap + (size_t)(it * 32) * KBIG);
        rb[it] = *reinterpret_cast<const float4*>(Bp + (size_t)(it * 32) * KBIG);
    }
#pragma unroll
    for (int it = 0; it < 4; it++) {
        *reinterpret_cast<float4*>(&As[r0 + it * 32][q]) = ra[it];
        *reinterpret_cast<float4*>(&Bs[r0 + it * 32][q]) = rb[it];
    }
    __syncthreads();

#pragma unroll 1
    for (int kt = 0; kt < KTILES; kt++) {
        if (kt + 1 < KTILES) {
#pragma unroll
            for (int it = 0; it < 4; it++) {
                ra[it] = *reinterpret_cast<const float4*>(
                    Ap + (size_t)(it * 32) * KBIG + (kt + 1) * 32);
                rb[it] = *reinterpret_cast<const float4*>(
                    Bp + (size_t)(it * 32) * KBIG + (kt + 1) * 32);
            }
        }
#pragma unroll
        for (int kk = 0; kk < 4; kk++) {
            FragA af[4];
            FragBc bf[2];
#pragma unroll
            for (int i = 0; i < 4; i++)
                wmma::load_matrix_sync(af[i], &As[wm + i * 16][kk * 8], 36);
#pragma unroll
            for (int j = 0; j < 2; j++)
                wmma::load_matrix_sync(bf[j], &Bs[wn + j * 16][kk * 8], 36);
#pragma unroll
            for (int i = 0; i < 4; i++)
#pragma unroll
                for (int j = 0; j < 2; j++)
                    wmma::mma_sync(acc[i][j], af[i], bf[j], acc[i][j]);
        }
        __syncthreads();
        if (kt + 1 < KTILES) {
#pragma unroll
            for (int it = 0; it < 4; it++) {
                *reinterpret_cast<float4*>(&As[r0 + it * 32][q]) = ra[it];
                *reinterpret_cast<float4*>(&Bs[r0 + it * 32][q]) = rb[it];
            }
            __syncthreads();
        }
    }

#pragma unroll
    for (int i = 0; i < 4; i++)
#pragma unroll
        for (int j = 0; j < 2; j++)
            wmma::store_matrix_sync(&Cs[wm + i * 16][wn + j * 16], acc[i][j],
                                    132, wmma::mem_row_major);
    __syncthreads();

    {
        const int r  = tid >> 1;
        const int hh = tid & 1;
        const int s  = n0 / 768;
        const int nh = ((n0 - s * 768) >> 6) + hh;
        const float* bias = (s == 0) ? bq : (s == 1) ? bk : bv;
        const float* gam  = (s == 0) ? gq : (s == 1) ? gk : gv;
        const float* bet  = (s == 0) ? eq : (s == 1) ? ek : ev;
        float* outp       = (s == 0) ? g_qb : (s == 1) ? g_kb : g_vb;
        const int c0 = hh << 6;

        float mu = 0.f;
#pragma unroll
        for (int d = 0; d < 64; d++) mu += Cs[r][c0 + d] + bias[d];
        mu *= (1.f / 64.f);
        float var = 0.f;
#pragma unroll
        for (int d = 0; d < 64; d++) {
            float v = Cs[r][c0 + d] + bias[d] - mu;
            var += v * v;
        }
        var *= (1.f / 64.f);
        const float rs = rsqrtf(var + 1e-5f);

        const int bt = m0 + r;
        const int b = bt >> 6, t = bt & 63;
        const size_t obase = (((size_t)b * NHEAD + nh) * 64 + t) * 64;
#pragma unroll
        for (int d = 0; d < 64; d++) {
            float v = (Cs[r][c0 + d] + bias[d] - mu) * rs;
            outp[obase + d] = v * gam[d] + bet[d];
        }
    }
#endif
}

// ---------------------------------------------------------------------------
// K3: fused attention per (b,n), 512 threads
// ---------------------------------------------------------------------------
#define ATTN_SMEM_FLOATS (3 * 64 * 65 + 127 * 65 + 64 * 65)
#define ATTN_SMEM_BYTES  (ATTN_SMEM_FLOATS * 4)

__global__ void __launch_bounds__(512) attn_kernel(const float* __restrict__ rel)
{
    extern __shared__ float sm[];
    float (*qs)[65] = reinterpret_cast<float(*)[65]>(sm);
    float (*ks)[65] = reinterpret_cast<float(*)[65]>(sm + 4160);
    float (*vs)[65] = reinterpret_cast<float(*)[65]>(sm + 8320);
    float (*rt)[65] = reinterpret_cast<float(*)[65]>(sm + 12480);
    float (*ss)[65] = reinterpret_cast<float(*)[65]>(sm + 12480 + 127 * 65);

    const int bn = blockIdx.x;
    const int tid = threadIdx.x;
    const size_t base = (size_t)bn * 4096;

    for (int idx = tid; idx < 4096; idx += 512) {
        int t = idx >> 6, c = idx & 63;
        qs[t][c] = g_qb[base + idx];
        ks[t][c] = g_kb[base + idx];
        vs[t][c] = g_vb[base + idx];
    }
    for (int idx = tid; idx < 127 * 64; idx += 512)
        rt[idx >> 6][idx & 63] = rel[idx];
    __syncthreads();

    const int u = tid & 63, tq = tid >> 6;   // tq in 0..7
#pragma unroll 1
    for (int p = 0; p < 8; p++) {
        int t = p * 8 + tq;
        const float* rrow = rt[t - u + 63];
        float a1 = 0.f, a2 = 0.f;
#pragma unroll
        for (int c = 0; c < 64; c++) {
            float qv = qs[t][c];
            a1 += qv * ks[u][c];
            a2 += qv * rrow[c];
        }
        ss[t][u] = 0.125f * a1 + a2;
    }
    __syncthreads();

    if (tid < 64) {
        const int t = tid;
        float mx = -1e30f;
#pragma unroll 1
        for (int uu = 0; uu < 64; uu++) mx = fmaxf(mx, ss[t][uu]);
        float sum = 0.f;
#pragma unroll 1
        for (int uu = 0; uu < 64; uu++) {
            float e = __expf(ss[t][uu] - mx);
            ss[t][uu] = e;
            sum += e;
        }
        float inv = 1.f / sum;
#pragma unroll 1
        for (int uu = 0; uu < 64; uu++) ss[t][uu] *= inv;
    }
    __syncthreads();

    const int b = bn / NHEAD, nh = bn - b * NHEAD;
#pragma unroll 1
    for (int p = 0; p < 8; p++) {
        int t = p * 8 + tq;
        float o = qs[t][u];
#pragma unroll
        for (int uu = 0; uu < 64; uu++) o += ss[t][uu] * vs[uu][u];
        g_att[(size_t)(b * 64 + t) * 768 + nh * 64 + u] = o;
    }
}

// ---------------------------------------------------------------------------
// K4: output projection (1024 x 768 x 768) + bias (wmma; tiny)
// ---------------------------------------------------------------------------
#define PROJ_SMEM_BYTES (128 * 132 * 4)

__global__ void __launch_bounds__(256) proj_kernel(
    const float* __restrict__ B, const float* __restrict__ bias, float* __restrict__ C)
{
    extern __shared__ float smemf[];
    float (*As)[36]  = reinterpret_cast<float(*)[36]>(smemf);
    float (*Bs)[136] = reinterpret_cast<float(*)[136]>(smemf + 4608);
    float (*Cs)[132] = reinterpret_cast<float(*)[132]>(smemf);

    const int tid = threadIdx.x, warp = tid >> 5;
    const int m0 = blockIdx.y * 128, n0 = blockIdx.x * 128;
    const int wm = (warp >> 2) * 64, wn = (warp & 3) * 32;

    FragC acc[4][2];
#pragma unroll
    for (int i = 0; i < 4; i++)
#pragma unroll
        for (int j = 0; j < 2; j++) wmma::fill_fragment(acc[i][j], 0.f);

#pragma unroll 1
    for (int kt = 0; kt < 24; kt++) {
#pragma unroll
        for (int it = 0; it < 4; it++) {
            int idx = tid + it * 256;
            int r = idx >> 3, qq = (idx & 7) << 2;
            float4 v = *reinterpret_cast<const float4*>(
                g_att + (size_t)(m0 + r) * 768 + kt * 32 + qq);
            *reinterpret_cast<float4*>(&As[r][qq]) = cvt4(v);
        }
#pragma unroll
        for (int it = 0; it < 4; it++) {
            int idx = tid + it * 256;
            int r = idx >> 5, qq = (idx & 31) << 2;
            float4 v = *reinterpret_cast<const float4*>(
                B + (size_t)(kt * 32 + r) * 768 + n0 + qq);
            *reinterpret_cast<float4*>(&Bs[r][qq]) = cvt4(v);
        }
        __syncthreads();

#pragma unroll
        for (int kk = 0; kk < 4; kk++) {
            FragA af[4];
            FragB bf[2];
#pragma unroll
            for (int i = 0; i < 4; i++)
                wmma::load_matrix_sync(af[i], &As[wm + i * 16][kk * 8], 36);
#pragma unroll
            for (int j = 0; j < 2; j++)
                wmma::load_matrix_sync(bf[j], &Bs[kk * 8][wn + j * 16], 136);
#pragma unroll
            for (int i = 0; i < 4; i++)
#pragma unroll
                for (int j = 0; j < 2; j++)
                    wmma::mma_sync(acc[i][j], af[i], bf[j], acc[i][j]);
        }
        __syncthreads();
    }

#pragma unroll
    for (int i = 0; i < 4; i++)
#pragma unroll
        for (int j = 0; j < 2; j++)
            wmma::store_matrix_sync(&Cs[wm + i * 16][wn + j * 16], acc[i][j],
                                    132, wmma::mem_row_major);
    __syncthreads();

    {
        const int r = tid >> 1;
        const int c0 = (tid & 1) << 6;
#pragma unroll
        for (int d = 0; d < 64; d++) {
            int col = c0 + d;
            C[(size_t)(m0 + r) * 768 + n0 + col] = Cs[r][col] + bias[n0 + col];
        }
    }
}

// ---------------------------------------------------------------------------
// Orchestration
// ---------------------------------------------------------------------------
extern "C" void kernel_launch(void* const* d_in, const int* in_sizes, int n_in,
                              void* d_out, int out_size)
{
    const float* x      = (const float*)d_in[0];
    const float* W_qkv  = (const float*)d_in[1];
    const float* Wpq    = (const float*)d_in[2];
    const float* bpq    = (const float*)d_in[3];
    const float* Wpk    = (const float*)d_in[4];
    const float* bpk    = (const float*)d_in[5];
    const float* Wpv    = (const float*)d_in[6];
    const float* bpv    = (const float*)d_in[7];
    const float* g_q    = (const float*)d_in[8];
    const float* be_q   = (const float*)d_in[9];
    const float* g_k    = (const float*)d_in[10];
    const float* be_k   = (const float*)d_in[11];
    const float* g_v    = (const float*)d_in[12];
    const float* be_v   = (const float*)d_in[13];
    const float* rel    = (const float*)d_in[14];
    const float* W_proj = (const float*)d_in[15];
    const float* b_proj = (const float*)d_in[16];
    float* out = (float*)d_out;

    cudaFuncSetAttribute(qkv_pool_ln_tc,
                         cudaFuncAttributeMaxDynamicSharedMemorySize, K1_SMEM_BYTES);
    cudaFuncSetAttribute(proj_kernel,
                         cudaFuncAttributeMaxDynamicSharedMemorySize, PROJ_SMEM_BYTES);
    cudaFuncSetAttribute(attn_kernel,
                         cudaFuncAttributeMaxDynamicSharedMemorySize, ATTN_SMEM_BYTES);

    // K00: tiny Wp transpose (+ tf32 pre-round)
    transpose_wp_kernel<<<(3 * HW2 * 4096 + 255) / 256, 256>>>(Wpq, Wpk, Wpv);

    // K01: pre-round x to tf32 (enables cvt-free cp.async mainloop)
    preround_x_kernel<<<(BT * (KBIG / 4) + 255) / 256, 256>>>(x);

    // K0: WeffT precompute (K-major store, tf32-rounded)
    weff_kernel<<<dim3(6, 3 * HW2 * NHEAD), 256>>>(W_qkv);

    // K1: fused qkv+pool GEMM + bias + LayerNorm (tcgen05 async pipeline)
    qkv_pool_ln_tc<<<dim3(D3 / 128, BT / 128), 256, K1_SMEM_BYTES>>>(
        bpq, bpk, bpv, g_q, g_k, g_v, be_q, be_k, be_v);

    // K3: attention per (b,n)
    attn_kernel<<<16 * NHEAD, 512, ATTN_SMEM_BYTES>>>(rel);

    // K4: output projection + bias
    proj_kernel<<<dim3(768 / 128, BT / 128), 256, PROJ_SMEM_BYTES>>>(
        W_proj, b_proj, out);
}

// round 17
// speedup vs baseline: 1.3062x; 1.3062x over previous
#include <cuda_runtime.h>
#include <mma.h>
#include <cstdint>
#include <cstddef>

using namespace nvcuda;

// ---------------------------------------------------------------------------
// B=16, T=64, HW=7 (49), D=768, N=12 heads, C=64, EPS=1e-5
//   WeffT[s*768+n*64+d, hw*768+k] = sum_c W_qkv[k, s*768+n*64+c]*Wp_s[d,c,hw]
//   qkv_pooled[bt, nd] = sum_kk x[bt, kk] * WeffT[nd, kk]
// -> ONE GEMM (1024 x 2304 x 37632), epilogue bias+LayerNorm.
// K1 tcgen05 body, ROUND-17: WARP-SPECIALIZED pipeline.
//   288 threads: warps 0-7 = producers (cp.async + arrive.noinc),
//   warp 8 = consumer (wait full -> MMA -> commit empty).
//   Round-16 regression root cause: consumer lived inside producer warp 0,
//   so warp 0's next-iter cp.asyncs serialized behind the full-wait ->
//   pipeline depth collapsed to 1.
// ---------------------------------------------------------------------------
#define BT     1024
#define D3     2304
#define KBIG   37632        // 49*768
#define NHEAD  12
#define HW2    49
#define KTILES (KBIG / 32)  // 1176 (divisible by 4)

#if defined(__CUDA_ARCH_FEAT_SM103_ALL) || defined(__CUDA_ARCH_FEAT_SM100_ALL) || defined(__CUDA_ARCH_FEAT_SM101_ALL)
#define HAS_TCGEN05 1
#else
#define HAS_TCGEN05 0
#endif

// ---------------------------------------------------------------------------
// Device scratch (statics; no runtime allocation)
// ---------------------------------------------------------------------------
__device__ float g_weffT[(size_t)D3 * KBIG];   // [n_global][k_global], 346.8 MB
__device__ float g_xtf[(size_t)BT * KBIG];     // tf32-rounded x, 154 MB
__device__ float g_wpT[3 * HW2 * 64 * 64];     // Wp transposed [s][hw][c][d]
__device__ float g_qb[BT * 768];               // (B,N,T,C) post-LN q
__device__ float g_kb[BT * 768];
__device__ float g_vb[BT * 768];
__device__ float g_att[BT * 768];              // (B,T,768) attention out

// ---------------------------------------------------------------------------
// Common helpers
// ---------------------------------------------------------------------------
__device__ __forceinline__ float f2tf(float x) {
    uint32_t u;
    asm("cvt.rna.tf32.f32 %0, %1;" : "=r"(u) : "f"(x));
    return __uint_as_float(u);
}
__device__ __forceinline__ float4 cvt4(float4 v) {
    float4 w;
    w.x = f2tf(v.x); w.y = f2tf(v.y); w.z = f2tf(v.z); w.w = f2tf(v.w);
    return w;
}

typedef wmma::fragment<wmma::matrix_a, 16, 16, 8, wmma::precision::tf32, wmma::row_major> FragA;
typedef wmma::fragment<wmma::matrix_b, 16, 16, 8, wmma::precision::tf32, wmma::row_major> FragB;
typedef wmma::fragment<wmma::matrix_b, 16, 16, 8, wmma::precision::tf32, wmma::col_major> FragBc;
typedef wmma::fragment<wmma::accumulator, 16, 16, 8, float> FragC;

__device__ __forceinline__ uint32_t elect_one_pred() {
    uint32_t pred;
    asm volatile(
        "{\n\t.reg .pred p;\n\t"
        "elect.sync _|p, 0xFFFFFFFF;\n\t"
        "selp.b32 %0, 1, 0, p;\n\t}"
        : "=r"(pred));
    return pred;
}
__device__ __forceinline__ uint32_t smem_to_u32(const void* p) {
    uint32_t a;
    asm("{ .reg .u64 t; cvta.to.shared.u64 t, %1; cvt.u32.u64 %0, t; }"
        : "=r"(a) : "l"(p));
    return a;
}

#define MBARRIER_INIT(addr, cnt) \
    asm volatile("mbarrier.init.shared.b64 [%0], %1;" :: "r"(addr), "r"(cnt) : "memory")

#define MBARRIER_WAIT_PARITY(addr, par) do {                                   \
    uint32_t _m = (addr), _p = (par), _d;                                      \
    asm volatile(                                                              \
        "{\n\t.reg .pred p;\n\t"                                               \
        "mbarrier.try_wait.parity.acquire.cta.shared::cta.b64 p, [%1], %2;\n\t"\
        "selp.b32 %0, 1, 0, p;\n\t}"                                           \
        : "=r"(_d) : "r"(_m), "r"(_p) : "memory");                             \
    if (!_d) {                                                                 \
        asm volatile(                                                          \
            "{\n\t.reg .pred P1;\n\t"                                          \
            "WL_%=:\n\t"                                                       \
            "mbarrier.try_wait.parity.acquire.cta.shared::cta.b64 P1, [%0], %1, 0x989680;\n\t" \
            "@P1 bra.uni WD_%=;\n\t"                                           \
            "bra.uni WL_%=;\n\t"                                               \
            "WD_%=:\n\t}"                                                      \
            :: "r"(_m), "r"(_p) : "memory");                                   \
    }                                                                          \
} while (0)

#define SW128(off) ((off) ^ (((off) >> 3) & 0x70))

// cp.async (Ampere-style async copy; no tensormap needed)
#define CP_ASYNC16(dst_u32, src_ptr) \
    asm volatile("cp.async.cg.shared.global [%0], [%1], 16;" \
                 :: "r"(dst_u32), "l"(src_ptr) : "memory")
// .noinc: arrive WITHOUT pre-incrementing pending count (barrier pre-armed
// with 256). The plain form is +1-then-arrive = net zero = never flips.
#define CP_ASYNC_MBAR_ARRIVE(mb) \
    asm volatile("cp.async.mbarrier.arrive.noinc.shared.b64 [%0];" :: "r"(mb) : "memory")

// ---------------------------------------------------------------------------
// tcgen05-only helpers
// ---------------------------------------------------------------------------
#define TCGEN05_ALLOC(res, n) \
    asm volatile("tcgen05.alloc.cta_group::1.sync.aligned.shared::cta.b32 [%0], %1;" \
                 :: "r"((uint32_t)(res)), "r"((uint32_t)(n)) : "memory")
#define TCGEN05_DEALLOC(tm, n) \
    asm volatile("tcgen05.dealloc.cta_group::1.sync.aligned.b32 %0, %1;" \
                 :: "r"(tm), "r"((uint32_t)(n)))
#define TCGEN05_RELINQ() \
    asm volatile("tcgen05.relinquish_alloc_permit.cta_group::1.sync.aligned;")
#define TCGEN05_COMMIT(mb) \
    asm volatile("tcgen05.commit.cta_group::1.mbarrier::arrive::one.shared::cluster.b64 [%0];" \
                 :: "r"((uint32_t)(mb)) : "memory")
#define TCGEN05_FENCE_AFTER() \
    asm volatile("tcgen05.fence::after_thread_sync;" ::: "memory")
#define TCGEN05_FENCE_BEFORE() \
    asm volatile("tcgen05.fence::before_thread_sync;" ::: "memory")
#define TCGEN05_WAIT_LD() \
    asm volatile("tcgen05.wait::ld.sync.aligned;" ::: "memory")
#define FENCE_ASYNC_SHARED() \
    asm volatile("fence.proxy.async.shared::cta;" ::: "memory")

#define TCGEN05_LD_X32(r, tm)                                                  \
    asm volatile(                                                              \
        "tcgen05.ld.sync.aligned.32x32b.x32.b32 "                              \
        "{%0, %1, %2, %3, %4, %5, %6, %7, "                                    \
        " %8, %9, %10, %11, %12, %13, %14, %15, "                              \
        " %16, %17, %18, %19, %20, %21, %22, %23, "                            \
        " %24, %25, %26, %27, %28, %29, %30, %31}, [%32];"                     \
        : "=r"((r)[0]),  "=r"((r)[1]),  "=r"((r)[2]),  "=r"((r)[3]),           \
          "=r"((r)[4]),  "=r"((r)[5]),  "=r"((r)[6]),  "=r"((r)[7]),           \
          "=r"((r)[8]),  "=r"((r)[9]),  "=r"((r)[10]), "=r"((r)[11]),          \
          "=r"((r)[12]), "=r"((r)[13]), "=r"((r)[14]), "=r"((r)[15]),          \
          "=r"((r)[16]), "=r"((r)[17]), "=r"((r)[18]), "=r"((r)[19]),          \
          "=r"((r)[20]), "=r"((r)[21]), "=r"((r)[22]), "=r"((r)[23]),          \
          "=r"((r)[24]), "=r"((r)[25]), "=r"((r)[26]), "=r"((r)[27]),          \
          "=r"((r)[28]), "=r"((r)[29]), "=r"((r)[30]), "=r"((r)[31])           \
        : "r"(tm))

#define TCGEN05_MMA_TF32_SS(d_tmem, a_desc, b_desc, idesc, enable)             \
    asm volatile(                                                              \
        "{\n\t.reg .pred p;\n\t"                                               \
        "setp.ne.u32 p, %4, 0;\n\t"                                            \
        "tcgen05.mma.cta_group::1.kind::tf32 [%0], %1, %2, %3, {%5, %5, %5, %5}, p;\n\t" \
        "}"                                                                    \
        :: "r"(d_tmem), "l"(a_desc), "l"(b_desc), "r"(idesc),                  \
           "r"((uint32_t)(enable)), "r"(0u)                                    \
        : "memory")

// SW128 descriptor: layout=2, version=1 (Blackwell), SBO=64, LBO=1 (128B rows)
static constexpr uint64_t SMEM_DESC_BASE_SW128 =
    (uint64_t(2) << 61) | (uint64_t(1) << 46) | (uint64_t(64) << 32) | (uint64_t(1) << 16);
#define MAKE_SMEM_DESC(a) (SMEM_DESC_BASE_SW128 | ((uint64_t)((a) >> 4) & 0x3FFF))

// idesc kind::tf32: dformat F32=1 [4:5], atype TF32=2 [7:9], btype TF32=2
// [10:12], N/8 [17:22] = 16 (N=128), M/16 [24:28] = 8 (M=128)
#define IDESC_TF32 ((1u << 4) | (2u << 7) | (2u << 10) | (16u << 17) | (8u << 24))

// ---------------------------------------------------------------------------
// K00: transpose Wp (d,c,hw) -> g_wpT[s][hw][c][d]  (+ tf32 pre-round)
// ---------------------------------------------------------------------------
__global__ void __launch_bounds__(256) transpose_wp_kernel(
    const float* __restrict__ wq, const float* __restrict__ wk, const float* __restrict__ wv)
{
    int idx = blockIdx.x * 256 + threadIdx.x;
    if (idx >= 3 * HW2 * 4096) return;
    int s = idx / (HW2 * 4096);
    int r = idx - s * (HW2 * 4096);
    int d  = r & 63;
    int c  = (r >> 6) & 63;
    int hw = r >> 12;
    const float* w = (s == 0) ? wq : (s == 1) ? wk : wv;
    g_wpT[idx] = f2tf(w[d * (64 * HW2) + c * HW2 + hw]);
}

// ---------------------------------------------------------------------------
// K01: pre-round x to tf32 (float4 per thread)
// ---------------------------------------------------------------------------
__global__ void __launch_bounds__(256) preround_x_kernel(const float* __restrict__ x)
{
    size_t i = ((size_t)blockIdx.x * 256 + threadIdx.x) * 4;
    if (i >= (size_t)BT * KBIG) return;
    float4 v = *reinterpret_cast<const float4*>(x + i);
    *reinterpret_cast<float4*>(g_xtf + i) = cvt4(v);
}

// ---------------------------------------------------------------------------
// K0: WeffT precompute, stored [n_global][k_global] (K-major), tf32-rounded.
// ---------------------------------------------------------------------------
__global__ void __launch_bounds__(256) weff_kernel(const float* __restrict__ Wqkv)
{
    __shared__ float As[128][36];
    __shared__ float Bs[32][72];

    const int tid = threadIdx.x, warp = tid >> 5;
    const int y = blockIdx.y;
    const int s = y / (HW2 * NHEAD);
    const int rem = y - s * (HW2 * NHEAD);
    const int hw = rem / NHEAD;
    const int n  = rem - hw * NHEAD;
    const int m0 = blockIdx.x * 128;
    const int coloff = s * 768 + n * 64;
    const float* wpT = g_wpT + (size_t)(s * HW2 + hw) * 4096;
    const int wm = (warp >> 1) * 32;
    const int wn = (warp & 1) * 32;

    FragC acc[2][2];
#pragma unroll
    for (int i = 0; i < 2; i++)
#pragma unroll
        for (int j = 0; j < 2; j++) wmma::fill_fragment(acc[i][j], 0.f);

#pragma unroll
    for (int kt = 0; kt < 2; kt++) {
#pragma unroll
        for (int it = 0; it < 4; it++) {
            int idx = tid + it * 256;
            int r = idx >> 3, q = (idx & 7) << 2;
            float4 v = *reinterpret_cast<const float4*>(
                Wqkv + (size_t)(m0 + r) * D3 + coloff + kt * 32 + q);
            *reinterpret_cast<float4*>(&As[r][q]) = cvt4(v);
        }
#pragma unroll
        for (int it = 0; it < 2; it++) {
            int idx = tid + it * 256;
            int rr = idx >> 4, dd = (idx & 15) << 2;
            *reinterpret_cast<float4*>(&Bs[rr][dd]) =
                *reinterpret_cast<const float4*>(wpT + (kt * 32 + rr) * 64 + dd);
        }
        __syncthreads();

#pragma unroll
        for (int kk = 0; kk < 4; kk++) {
            FragA af[2];
            FragB bf[2];
#pragma unroll
            for (int i = 0; i < 2; i++)
                wmma::load_matrix_sync(af[i], &As[wm + i * 16][kk * 8], 36);
#pragma unroll
            for (int j = 0; j < 2; j++)
                wmma::load_matrix_sync(bf[j], &Bs[kk * 8][wn + j * 16], 72);
#pragma unroll
            for (int i = 0; i < 2; i++)
#pragma unroll
                for (int j = 0; j < 2; j++)
                    wmma::mma_sync(acc[i][j], af[i], bf[j], acc[i][j]);
        }
        __syncthreads();
    }

#pragma unroll
    for (int i = 0; i < 2; i++)
#pragma unroll
        for (int j = 0; j < 2; j++) {
#pragma unroll
            for (int e = 0; e < acc[i][j].num_elements; e++)
                acc[i][j].x[e] = f2tf(acc[i][j].x[e]);
            float* dst = g_weffT +
                (size_t)(coloff + wn + j * 16) * KBIG + (hw * 768 + m0 + wm + i * 16);
            wmma::store_matrix_sync(dst, acc[i][j], KBIG, wmma::mem_col_major);
        }
}

// ---------------------------------------------------------------------------
// K1: fused GEMM (1024 x 2304 x 37632) + bias + LayerNorm epilogue.
// grid (18, 8) = 144 CTAs, 288 threads (warps 0-7 producers, warp 8 consumer).
// ---------------------------------------------------------------------------
#define ST_A(s)  ((s) * 16384)
#define ST_B(s)  (65536 + (s) * 16384)
#define OFF_TM   131072
#define OFF_FULL 131080                     // full[4] : 8B each
#define OFF_EMPT 131112                     // empty[4]: 8B each
#define K1_SMEM_BYTES 131200
#define K1_THREADS 288

__global__ void __launch_bounds__(K1_THREADS, 1) qkv_pool_ln_tc(
    const float* __restrict__ bq, const float* __restrict__ bk, const float* __restrict__ bv,
    const float* __restrict__ gq, const float* __restrict__ gk, const float* __restrict__ gv,
    const float* __restrict__ eq, const float* __restrict__ ek, const float* __restrict__ ev)
{
#if HAS_TCGEN05
    // =======================================================================
    // tcgen05 tf32 SS body — warp-specialized producers/consumer
    // =======================================================================
    extern __shared__ char smem[];
    const uint32_t sb = smem_to_u32(smem);
    const int tid = threadIdx.x, warp = tid >> 5, lane = tid & 31;
    const bool is_prod = (tid < 256);
    const int m0 = blockIdx.y * 128, n0 = blockIdx.x * 128;

    if (warp == 8) TCGEN05_ALLOC(sb + OFF_TM, 128);
    if (tid == 0) {
#pragma unroll
        for (int s = 0; s < 4; s++) {
            MBARRIER_INIT(sb + OFF_FULL + s * 8, 256);  // 256 noinc arrives
            MBARRIER_INIT(sb + OFF_EMPT + s * 8, 1);    // 1 commit arrive
        }
    }
    __syncthreads();
    uint32_t tmem;
    asm volatile("ld.shared.b32 %0, [%1];" : "=r"(tmem) : "r"(sb + OFF_TM));

    const int rA  = tid >> 3;              // base row, +32 per it (producers)
    const int q16 = (tid & 7) << 4;        // byte offset within 128B row
    uint32_t swoff[4];
#pragma unroll
    for (int it = 0; it < 4; it++)
        swoff[it] = SW128((uint32_t)(((it * 32 + rA) & 127) * 128 + q16));

    const float* Ap = g_xtf   + (size_t)(m0 + (rA & 31)) * KBIG + (q16 >> 2);
    const float* Bp = g_weffT + (size_t)(n0 + (rA & 31)) * KBIG + (q16 >> 2);
    // note: for producers rA<32 so (rA&31)==rA; consumer warp never uses these

    uint32_t cons = 0;
    if (warp == 8) cons = elect_one_pred();

    int ph_e[4] = {0, 0, 0, 0};    // producer empty phases
    int ph_f[4] = {0, 0, 0, 0};    // consumer full phases

#pragma unroll 1
    for (int i = 0; i < KTILES; i++) {
        const int s = i & 3;
        if (is_prod) {
            if (i >= 4) {
                MBARRIER_WAIT_PARITY(sb + OFF_EMPT + s * 8, ph_e[s]);
                ph_e[s] ^= 1;
            }
            const int k0 = i * 32;
            const uint32_t abase = sb + ST_A(s);
            const uint32_t bbase = sb + ST_B(s);
#pragma unroll
            for (int it = 0; it < 4; it++) {
                CP_ASYNC16(abase + swoff[it], Ap + (size_t)(it * 32) * KBIG + k0);
                CP_ASYNC16(bbase + swoff[it], Bp + (size_t)(it * 32) * KBIG + k0);
            }
            CP_ASYNC_MBAR_ARRIVE(sb + OFF_FULL + s * 8);
        } else if (cons) {
            MBARRIER_WAIT_PARITY(sb + OFF_FULL + s * 8, ph_f[s]);
            ph_f[s] ^= 1;
            FENCE_ASYNC_SHARED();
            const uint64_t ad = MAKE_SMEM_DESC(sb + ST_A(s));
            const uint64_t bd = MAKE_SMEM_DESC(sb + ST_B(s));
#pragma unroll
            for (int kk = 0; kk < 4; kk++)
                TCGEN05_MMA_TF32_SS(tmem, ad + kk * 2, bd + kk * 2, IDESC_TF32,
                                    (i > 0) || (kk > 0));
            TCGEN05_COMMIT(sb + OFF_EMPT + s * 8);
        }
    }

    // drain: producers wait the final commits (ensures ALL MMAs complete)
    if (is_prod) {
#pragma unroll
        for (int s = 0; s < 4; s++)
            MBARRIER_WAIT_PARITY(sb + OFF_EMPT + s * 8, ph_e[s]);
    }
    __syncthreads();
    TCGEN05_FENCE_AFTER();

    // ---- epilogue: warps 0-3 read D per-head (64 cols at a time) + LN ----
    if (warp < 4) {
        const int row = warp * 32 + lane;
        const int bt = m0 + row;
        const int bb = bt >> 6, t = bt & 63;
        const int s  = n0 / 768;
        const int nh0 = (n0 - s * 768) >> 6;
        const float* bias = (s == 0) ? bq : (s == 1) ? bk : bv;
        const float* gam  = (s == 0) ? gq : (s == 1) ? gk : gv;
        const float* bet  = (s == 0) ? eq : (s == 1) ? ek : ev;
        float* outp       = (s == 0) ? g_qb : (s == 1) ? g_kb : g_vb;

#pragma unroll
        for (int hh = 0; hh < 2; hh++) {
            float dreg[64];
            uint32_t* du = reinterpret_cast<uint32_t*>(dreg);
            TCGEN05_LD_X32(du,      tmem + hh * 64);
            TCGEN05_LD_X32(du + 32, tmem + hh * 64 + 32);
            TCGEN05_WAIT_LD();

            float mu = 0.f;
#pragma unroll
            for (int d = 0; d < 64; d++) mu += dreg[d] + __ldg(bias + d);
            mu *= (1.f / 64.f);
            float var = 0.f;
#pragma unroll
            for (int d = 0; d < 64; d++) {
                float v = dreg[d] + __ldg(bias + d) - mu;
                var += v * v;
            }
            var *= (1.f / 64.f);
            const float rs = rsqrtf(var + 1e-5f);
            const size_t obase = (((size_t)bb * NHEAD + nh0 + hh) * 64 + t) * 64;
#pragma unroll
            for (int d = 0; d < 64; d++) {
                float v = (dreg[d] + __ldg(bias + d) - mu) * rs;
                outp[obase + d] = v * __ldg(gam + d) + __ldg(bet + d);
            }
        }
        TCGEN05_FENCE_BEFORE();
    }
    __syncthreads();
    if (warp == 8) {
        TCGEN05_RELINQ();
        TCGEN05_DEALLOC(tmem, 128);
    }
#else
    // =======================================================================
    // wmma HMMA tf32 fallback body (288 threads: warp 8 inert)
    // =======================================================================
    extern __shared__ char smem_c[];
    float* smemf = reinterpret_cast<float*>(smem_c);
    float (*As)[36]  = reinterpret_cast<float(*)[36]>(smemf);           // [m][k]
    float (*Bs)[36]  = reinterpret_cast<float(*)[36]>(smemf + 4608);    // [n][k]
    float (*Cs)[132] = reinterpret_cast<float(*)[132]>(smemf);          // reused

    const int tid = threadIdx.x, warp = tid >> 5;
    const bool act = (tid < 256);
    const int m0 = blockIdx.y * 128, n0 = blockIdx.x * 128;
    const int wm = ((warp & 7) >> 2) * 64, wn = (warp & 3) * 32;

    const int r0 = (tid & 255) >> 3;
    const int q  = (tid & 7) << 2;

    const float* Ap = g_xtf   + (size_t)(m0 + r0) * KBIG + q;
    const float* Bp = g_weffT + (size_t)(n0 + r0) * KBIG + q;

    FragC acc[4][2];
#pragma unroll
    for (int i = 0; i < 4; i++)
#pragma unroll
        for (int j = 0; j < 2; j++) wmma::fill_fragment(acc[i][j], 0.f);

    if (act) {
        float4 ra[4], rb[4];
#pragma unroll
        for (int it = 0; it < 4; it++) {
            ra[it] = *reinterpret_cast<const float4*>(Ap + (size_t)(it * 32) * KBIG);
            rb[it] = *reinterpret_cast<const float4*>(Bp + (size_t)(it * 32) * KBIG);
        }
#pragma unroll
        for (int it = 0; it < 4; it++) {
            *reinterpret_cast<float4*>(&As[r0 + it * 32][q]) = ra[it];
            *reinterpret_cast<float4*>(&Bs[r0 + it * 32][q]) = rb[it];
        }
    }
    __syncthreads();

#pragma unroll 1
    for (int kt = 0; kt < KTILES; kt++) {
        float4 ra[4], rb[4];
        if (act && kt + 1 < KTILES) {
#pragma unroll
            for (int it = 0; it < 4; it++) {
                ra[it] = *reinterpret_cast<const float4*>(
                    Ap + (size_t)(it * 32) * KBIG + (kt + 1) * 32);
                rb[it] = *reinterpret_cast<const float4*>(
                    Bp + (size_t)(it * 32) * KBIG + (kt + 1) * 32);
            }
        }
        if (warp < 8) {
#pragma unroll
            for (int kk = 0; kk < 4; kk++) {
                FragA af[4];
                FragBc bf[2];
#pragma unroll
                for (int i = 0; i < 4; i++)
                    wmma::load_matrix_sync(af[i], &As[wm + i * 16][kk * 8], 36);
#pragma unroll
                for (int j = 0; j < 2; j++)
                    wmma::load_matrix_sync(bf[j], &Bs[wn + j * 16][kk * 8], 36);
#pragma unroll
                for (int i = 0; i < 4; i++)
#pragma unroll
                    for (int j = 0; j < 2; j++)
                        wmma::mma_sync(acc[i][j], af[i], bf[j], acc[i][j]);
            }
        }
        __syncthreads();
        if (act && kt + 1 < KTILES) {
#pragma unroll
            for (int it = 0; it < 4; it++) {
                *reinterpret_cast<float4*>(&As[r0 + it * 32][q]) = ra[it];
                *reinterpret_cast<float4*>(&Bs[r0 + it * 32][q]) = rb[it];
            }
        }
        __syncthreads();
    }

    if (warp < 8) {
#pragma unroll
        for (int i = 0; i < 4; i++)
#pragma unroll
            for (int j = 0; j < 2; j++)
                wmma::store_matrix_sync(&Cs[wm + i * 16][wn + j * 16], acc[i][j],
                                        132, wmma::mem_row_major);
    }
    __syncthreads();

    if (act) {
        const int r  = tid >> 1;
        const int hh = tid & 1;
        const int s  = n0 / 768;
        const int nh = ((n0 - s * 768) >> 6) + hh;
        const float* bias = (s == 0) ? bq : (s == 1) ? bk : bv;
        const float* gam  = (s == 0) ? gq : (s == 1) ? gk : gv;
        const float* bet  = (s == 0) ? eq : (s == 1) ? ek : ev;
        float* outp       = (s == 0) ? g_qb : (s == 1) ? g_kb : g_vb;
        const int c0 = hh << 6;

        float mu = 0.f;
#pragma unroll
        for (int d = 0; d < 64; d++) mu += Cs[r][c0 + d] + bias[d];
        mu *= (1.f / 64.f);
        float var = 0.f;
#pragma unroll
        for (int d = 0; d < 64; d++) {
            float v = Cs[r][c0 + d] + bias[d] - mu;
            var += v * v;
        }
        var *= (1.f / 64.f);
        const float rs = rsqrtf(var + 1e-5f);

        const int bt = m0 + r;
        const int b = bt >> 6, t = bt & 63;
        const size_t obase = (((size_t)b * NHEAD + nh) * 64 + t) * 64;
#pragma unroll
        for (int d = 0; d < 64; d++) {
            float v = (Cs[r][c0 + d] + bias[d] - mu) * rs;
            outp[obase + d] = v * gam[d] + bet[d];
        }
    }
#endif
}

// ---------------------------------------------------------------------------
// K3: fused attention per (b,n), 512 threads
// ---------------------------------------------------------------------------
#define ATTN_SMEM_FLOATS (3 * 64 * 65 + 127 * 65 + 64 * 65)
#define ATTN_SMEM_BYTES  (ATTN_SMEM_FLOATS * 4)

__global__ void __launch_bounds__(512) attn_kernel(const float* __restrict__ rel)
{
    extern __shared__ float sm[];
    float (*qs)[65] = reinterpret_cast<float(*)[65]>(sm);
    float (*ks)[65] = reinterpret_cast<float(*)[65]>(sm + 4160);
    float (*vs)[65] = reinterpret_cast<float(*)[65]>(sm + 8320);
    float (*rt)[65] = reinterpret_cast<float(*)[65]>(sm + 12480);
    float (*ss)[65] = reinterpret_cast<float(*)[65]>(sm + 12480 + 127 * 65);

    const int bn = blockIdx.x;
    const int tid = threadIdx.x;
    const size_t base = (size_t)bn * 4096;

    for (int idx = tid; idx < 4096; idx += 512) {
        int t = idx >> 6, c = idx & 63;
        qs[t][c] = g_qb[base + idx];
        ks[t][c] = g_kb[base + idx];
        vs[t][c] = g_vb[base + idx];
    }
    for (int idx = tid; idx < 127 * 64; idx += 512)
        rt[idx >> 6][idx & 63] = rel[idx];
    __syncthreads();

    const int u = tid & 63, tq = tid >> 6;   // tq in 0..7
#pragma unroll 1
    for (int p = 0; p < 8; p++) {
        int t = p * 8 + tq;
        const float* rrow = rt[t - u + 63];
        float a1 = 0.f, a2 = 0.f;
#pragma unroll
        for (int c = 0; c < 64; c++) {
            float qv = qs[t][c];
            a1 += qv * ks[u][c];
            a2 += qv * rrow[c];
        }
        ss[t][u] = 0.125f * a1 + a2;
    }
    __syncthreads();

    if (tid < 64) {
        const int t = tid;
        float mx = -1e30f;
#pragma unroll 1
        for (int uu = 0; uu < 64; uu++) mx = fmaxf(mx, ss[t][uu]);
        float sum = 0.f;
#pragma unroll 1
        for (int uu = 0; uu < 64; uu++) {
            float e = __expf(ss[t][uu] - mx);
            ss[t][uu] = e;
            sum += e;
        }
        float inv = 1.f / sum;
#pragma unroll 1
        for (int uu = 0; uu < 64; uu++) ss[t][uu] *= inv;
    }
    __syncthreads();

    const int b = bn / NHEAD, nh = bn - b * NHEAD;
#pragma unroll 1
    for (int p = 0; p < 8; p++) {
        int t = p * 8 + tq;
        float o = qs[t][u];
#pragma unroll
        for (int uu = 0; uu < 64; uu++) o += ss[t][uu] * vs[uu][u];
        g_att[(size_t)(b * 64 + t) * 768 + nh * 64 + u] = o;
    }
}

// ---------------------------------------------------------------------------
// K4: output projection (1024 x 768 x 768) + bias (wmma; tiny)
// ---------------------------------------------------------------------------
#define PROJ_SMEM_BYTES (128 * 132 * 4)

__global__ void __launch_bounds__(256) proj_kernel(
    const float* __restrict__ B, const float* __restrict__ bias, float* __restrict__ C)
{
    extern __shared__ float smemf[];
    float (*As)[36]  = reinterpret_cast<float(*)[36]>(smemf);
    float (*Bs)[136] = reinterpret_cast<float(*)[136]>(smemf + 4608);
    float (*Cs)[132] = reinterpret_cast<float(*)[132]>(smemf);

    const int tid = threadIdx.x, warp = tid >> 5;
    const int m0 = blockIdx.y * 128, n0 = blockIdx.x * 128;
    const int wm = (warp >> 2) * 64, wn = (warp & 3) * 32;

    FragC acc[4][2];
#pragma unroll
    for (int i = 0; i < 4; i++)
#pragma unroll
        for (int j = 0; j < 2; j++) wmma::fill_fragment(acc[i][j], 0.f);

#pragma unroll 1
    for (int kt = 0; kt < 24; kt++) {
#pragma unroll
        for (int it = 0; it < 4; it++) {
            int idx = tid + it * 256;
            int r = idx >> 3, qq = (idx & 7) << 2;
            float4 v = *reinterpret_cast<const float4*>(
                g_att + (size_t)(m0 + r) * 768 + kt * 32 + qq);
            *reinterpret_cast<float4*>(&As[r][qq]) = cvt4(v);
        }
#pragma unroll
        for (int it = 0; it < 4; it++) {
            int idx = tid + it * 256;
            int r = idx >> 5, qq = (idx & 31) << 2;
            float4 v = *reinterpret_cast<const float4*>(
                B + (size_t)(kt * 32 + r) * 768 + n0 + qq);
            *reinterpret_cast<float4*>(&Bs[r][qq]) = cvt4(v);
        }
        __syncthreads();

#pragma unroll
        for (int kk = 0; kk < 4; kk++) {
            FragA af[4];
            FragB bf[2];
#pragma unroll
            for (int i = 0; i < 4; i++)
                wmma::load_matrix_sync(af[i], &As[wm + i * 16][kk * 8], 36);
#pragma unroll
            for (int j = 0; j < 2; j++)
                wmma::load_matrix_sync(bf[j], &Bs[kk * 8][wn + j * 16], 136);
#pragma unroll
            for (int i = 0; i < 4; i++)
#pragma unroll
                for (int j = 0; j < 2; j++)
                    wmma::mma_sync(acc[i][j], af[i], bf[j], acc[i][j]);
        }
        __syncthreads();
    }

#pragma unroll
    for (int i = 0; i < 4; i++)
#pragma unroll
        for (int j = 0; j < 2; j++)
            wmma::store_matrix_sync(&Cs[wm + i * 16][wn + j * 16], acc[i][j],
                                    132, wmma::mem_row_major);
    __syncthreads();

    {
        const int r = tid >> 1;
        const int c0 = (tid & 1) << 6;
#pragma unroll
        for (int d = 0; d < 64; d++) {
            int col = c0 + d;
            C[(size_t)(m0 + r) * 768 + n0 + col] = Cs[r][col] + bias[n0 + col];
        }
    }
}

// ---------------------------------------------------------------------------
// Orchestration
// ---------------------------------------------------------------------------
extern "C" void kernel_launch(void* const* d_in, const int* in_sizes, int n_in,
                              void* d_out, int out_size)
{
    const float* x      = (const float*)d_in[0];
    const float* W_qkv  = (const float*)d_in[1];
    const float* Wpq    = (const float*)d_in[2];
    const float* bpq    = (const float*)d_in[3];
    const float* Wpk    = (const float*)d_in[4];
    const float* bpk    = (const float*)d_in[5];
    const float* Wpv    = (const float*)d_in[6];
    const float* bpv    = (const float*)d_in[7];
    const float* g_q    = (const float*)d_in[8];
    const float* be_q   = (const float*)d_in[9];
    const float* g_k    = (const float*)d_in[10];
    const float* be_k   = (const float*)d_in[11];
    const float* g_v    = (const float*)d_in[12];
    const float* be_v   = (const float*)d_in[13];
    const float* rel    = (const float*)d_in[14];
    const float* W_proj = (const float*)d_in[15];
    const float* b_proj = (const float*)d_in[16];
    float* out = (float*)d_out;

    cudaFuncSetAttribute(qkv_pool_ln_tc,
                         cudaFuncAttributeMaxDynamicSharedMemorySize, K1_SMEM_BYTES);
    cudaFuncSetAttribute(proj_kernel,
                         cudaFuncAttributeMaxDynamicSharedMemorySize, PROJ_SMEM_BYTES);
    cudaFuncSetAttribute(attn_kernel,
                         cudaFuncAttributeMaxDynamicSharedMemorySize, ATTN_SMEM_BYTES);

    // K00: tiny Wp transpose (+ tf32 pre-round)
    transpose_wp_kernel<<<(3 * HW2 * 4096 + 255) / 256, 256>>>(Wpq, Wpk, Wpv);

    // K01: pre-round x to tf32 (enables cvt-free cp.async mainloop)
    preround_x_kernel<<<(BT * (KBIG / 4) + 255) / 256, 256>>>(x);

    // K0: WeffT precompute (K-major store, tf32-rounded)
    weff_kernel<<<dim3(6, 3 * HW2 * NHEAD), 256>>>(W_qkv);

    // K1: fused qkv+pool GEMM + bias + LayerNorm (warp-specialized tcgen05)
    qkv_pool_ln_tc<<<dim3(D3 / 128, BT / 128), K1_THREADS, K1_SMEM_BYTES>>>(
        bpq, bpk, bpv, g_q, g_k, g_v, be_q, be_k, be_v);

    // K3: attention per (b,n)
    attn_kernel<<<16 * NHEAD, 512, ATTN_SMEM_BYTES>>>(rel);

    // K4: output projection + bias
    proj_kernel<<<dim3(768 / 128, BT / 128), 256, PROJ_SMEM_BYTES>>>(
        W_proj, b_proj, out);
}